// round 12
// baseline (speedup 1.0000x reference)
#include <cuda_runtime.h>
#include <cuda_fp16.h>
#include <cstdint>

#define BB 64
#define TT 32
#define NMAXX 64
#define HH 256      // output dim (N of GEMM)
#define HID 128     // mid dim (K of GEMM)
#define MT 64       // rows per team tile
#define NTH 512     // 16 warps: two independent teams of 8 warps

// main-kernel dynamic smem (1024-aligned): A[team][buf] 4x16KB, B 64KB
#define OFF_B 65536
#define DYN_SMEM (131072 + 1024)

__device__ int g_ticket;
__device__ __align__(16) char g_A[33554432];   // staged A fp16, fragment/swizzle layout

__global__ void reset_ticket() { g_ticket = 0; }

__device__ __forceinline__ uint32_t smem_u32(const void* p) {
    uint32_t a;
    asm("{ .reg .u64 t; cvta.to.shared.u64 t, %1; cvt.u32.u64 %0, t; }" : "=r"(a) : "l"(p));
    return a;
}
__device__ __forceinline__ void sts32(uint32_t a, uint32_t v) {
    asm volatile("st.shared.b32 [%0], %1;" :: "r"(a), "r"(v) : "memory");
}
__device__ __forceinline__ uint4 ldsm4(uint32_t a) {
    uint4 r;
    asm volatile("ldmatrix.sync.aligned.m8n8.x4.shared.b16 {%0,%1,%2,%3}, [%4];"
                 : "=r"(r.x), "=r"(r.y), "=r"(r.z), "=r"(r.w) : "r"(a));
    return r;
}
#define MMA4(c, a, bb0, bb1) \
    asm volatile("mma.sync.aligned.m16n8k16.row.col.f32.f16.f16.f32 " \
                 "{%0,%1,%2,%3},{%4,%5,%6,%7},{%8,%9},{%0,%1,%2,%3};" \
                 : "+f"((c)[0]), "+f"((c)[1]), "+f"((c)[2]), "+f"((c)[3]) \
                 : "r"((a).x), "r"((a).y), "r"((a).z), "r"((a).w), "r"(bb0), "r"(bb1))
#define CP_ASYNC16(sm, gp) \
    asm volatile("cp.async.cg.shared.global [%0], [%1], 16;" :: "r"(sm), "l"(gp) : "memory")
#define CP_COMMIT() asm volatile("cp.async.commit_group;" ::: "memory")
#define CP_WAIT1()  asm volatile("cp.async.wait_group 1;" ::: "memory")

// ---------------- convert kernel: layer-1 -> fp16 fragments in g_A, + zerofill ----------------
__global__ __launch_bounds__(256)
void convert_kernel(const float* __restrict__ bbox,
                    const float* __restrict__ W1, const float* __restrict__ b1,
                    const int* __restrict__ npf, float* __restrict__ out,
                    int TOTROWS, int nrowblk) {
    const int tid = threadIdx.x;

    if ((int)blockIdx.x >= nrowblk) {
        // zerofill one invalid padded slot (32KB)
        int slot = blockIdx.x - nrowblk;
        int b = slot >> 6, s = slot & 63;
        if (s < npf[b]) return;
        float4* dst = reinterpret_cast<float4*>(out + ((size_t)s * (BB * TT) + (size_t)b * TT) * HH);
        float4 z = make_float4(0.f, 0.f, 0.f, 0.f);
        #pragma unroll
        for (int i = 0; i < 8; ++i) dst[tid + i * 256] = z;
        return;
    }

    __shared__ float W1s[4 * HID], b1s[HID];
    for (int i = tid; i < 4 * HID; i += 256) W1s[i] = W1[i];
    if (tid < HID) b1s[tid] = b1[tid];
    __syncthreads();

    // block = 16 rows x 16 chunks; thread: row grow, chunk c (8 k-cols -> one uint4)
    const int grow = blockIdx.x * 16 + (tid >> 4);
    const int c = tid & 15;
    float4 x = make_float4(0.f, 0.f, 0.f, 0.f);
    if (grow < TOTROWS) x = __ldg(reinterpret_cast<const float4*>(bbox) + grow);

    uint32_t hw[4];
    #pragma unroll
    for (int p = 0; p < 4; ++p) {
        int j = 8 * c + 2 * p;
        float h0 = fmaf(x.x, W1s[j],     fmaf(x.y, W1s[HID + j],     fmaf(x.z, W1s[2 * HID + j],     fmaf(x.w, W1s[3 * HID + j],     b1s[j]))));
        float h1 = fmaf(x.x, W1s[j + 1], fmaf(x.y, W1s[HID + j + 1], fmaf(x.z, W1s[2 * HID + j + 1], fmaf(x.w, W1s[3 * HID + j + 1], b1s[j + 1]))));
        __half2 hv = __floats2half2_rn(fmaxf(h0, 0.f), fmaxf(h1, 0.f));
        hw[p] = *reinterpret_cast<uint32_t*>(&hv);
    }
    const int tile = grow >> 6, cr = grow & 63;
    size_t off = (size_t)tile * 16384 + (size_t)cr * 256 + (size_t)((c ^ (cr & 7)) << 4);
    *reinterpret_cast<uint4*>(g_A + off) = make_uint4(hw[0], hw[1], hw[2], hw[3]);
}

// ---------------- main GEMM kernel ----------------
__global__ __launch_bounds__(NTH, 1)
void mma_kernel(const float* __restrict__ W2, const float* __restrict__ b2,
                const int* __restrict__ npf,
                float* __restrict__ out, int TOTROWS, int ntiles) {
    extern __shared__ char smraw[];
    __shared__ float b2s[HH];
    __shared__ int sn[BB], st[BB + 1];
    __shared__ int orow_s[2][2][MT];   // [team][buf][row]
    __shared__ int nt_s[2];

    const int tid  = threadIdx.x;
    const int lane = tid & 31, wid = tid >> 5;
    const int team = wid >> 3;
    const int hw   = wid & 7;
    const int htid = tid & 255;

    const uint32_t sb  = (smem_u32(smraw) + 1023) & ~1023u;
    const uint32_t A_T = sb + (uint32_t)team * 32768u;    // two 16KB bufs per team
    const uint32_t B_S = sb + OFF_B;

    if (tid < HH) b2s[tid] = b2[tid];
    if (tid >= HH && tid < HH + BB) sn[tid - HH] = npf[tid - HH];
    __syncthreads();
    if (tid == 0) {
        int s = 0;
        #pragma unroll
        for (int i = 0; i < BB; ++i) { st[i] = s; s += sn[i]; }
        st[BB] = s;
    }

    // ---- convert B = W2^T -> f16, permuted rows + 16B XOR swizzle ----
    {
        const int n  = tid & 255;
        const int kh = tid >> 8;
        const int c = n & 31;
        const int s = 16 * ((c >> 2) & 1) + 8 * ((c >> 1) & 1) + 2 * (c >> 3) + (c & 1);
        const int m = (n & ~31) | s;
        const uint32_t mb = (uint32_t)m * 256u;
        const uint32_t mx = (uint32_t)(m & 7);
        #pragma unroll 4
        for (int q = 0; q < 32; ++q) {
            int jp = kh * 32 + q;
            int j = 2 * jp;
            float w0 = __ldg(&W2[(size_t)j * HH + n]);
            float w1 = __ldg(&W2[(size_t)(j + 1) * HH + n]);
            __half2 hi = __floats2half2_rn(w0, w1);
            uint32_t byte = mb + ((((uint32_t)jp >> 2) ^ mx) << 4) + (((uint32_t)jp & 3) << 2);
            sts32(B_S + byte, *reinterpret_cast<uint32_t*>(&hi));
        }
    }

    // ---- geometry (identical to r11) ----
    const uint32_t xorv = (uint32_t)(lane & 7);
    const int a_row = (lane & 7) + ((lane >> 3) & 1) * 8;
    const uint32_t a_chi = (uint32_t)(lane >> 4);
    const int b_row = (lane & 7) + (lane >> 4) * 8;
    const uint32_t b_chi = (uint32_t)((lane >> 3) & 1);
    const uint32_t aOff0 = (uint32_t)a_row * 256u;
    uint32_t bBase[2];
    #pragma unroll
    for (int j = 0; j < 2; ++j)
        bBase[j] = B_S + (uint32_t)(hw * 32 + j * 16 + b_row) * 256u;
    const int cb = hw * 32 + (lane & 3) * 8;
    const int barid = team + 1;

    // ---- helpers ----
    auto issue_tile = [&](int tile, int buf) {
        if (tile < ntiles) {
            const char* src = g_A + (size_t)tile * 16384 + (size_t)htid * 64;
            uint32_t dst = A_T + (uint32_t)buf * 16384u + (uint32_t)htid * 64u;
            #pragma unroll
            for (int k = 0; k < 4; ++k) CP_ASYNC16(dst + k * 16, src + k * 16);
        }
        CP_COMMIT();
        if (htid < MT) {
            int grow = tile * MT + htid;
            int orow = -1;
            if (tile < ntiles && grow < TOTROWS) {
                int box = grow >> 5;
                int lo = 0, hi = BB - 1;
                #pragma unroll
                for (int step = 0; step < 6; ++step) {
                    int mid = (lo + hi + 1) >> 1;
                    if (st[mid] <= box) lo = mid; else hi = mid - 1;
                }
                orow = (box - st[lo]) * (BB * TT) + lo * TT + (grow & 31);
            }
            orow_s[team][buf][htid] = orow;
        }
    };

    // ---- priming: two tickets, two buffers in flight ----
    if (htid == 0) nt_s[team] = atomicAdd(&g_ticket, 1);
    __syncthreads();   // B smem + scan + first ticket visible (last full-block barrier)
    int cur = nt_s[team];
    issue_tile(cur, 0);
    if (htid == 0) nt_s[team] = atomicAdd(&g_ticket, 1);
    asm volatile("bar.sync %0, %1;" :: "r"(barid), "r"(256) : "memory");
    int nxt = nt_s[team];
    issue_tile(nxt, 1);

    int pb = 0;
    while (cur < ntiles) {
        CP_WAIT1();                                                       // buf pb data arrived (this thread)
        asm volatile("bar.sync %0, %1;" :: "r"(barid), "r"(256) : "memory");  // team-wide visibility

        // ---- MMA mainloop: single fp16 product, K=128, warp tile 64x32 ----
        float acc[4][4][4];
        #pragma unroll
        for (int mf = 0; mf < 4; ++mf)
            #pragma unroll
            for (int q = 0; q < 4; ++q)
                #pragma unroll
                for (int e = 0; e < 4; ++e) acc[mf][q][e] = 0.f;

        const uint32_t aB = A_T + (uint32_t)pb * 16384u + aOff0;
        #pragma unroll 1
        for (int kc = 0; kc < 8; ++kc) {
            uint32_t kxa = ((((uint32_t)kc << 1) + a_chi) ^ xorv) << 4;
            uint32_t kxb = ((((uint32_t)kc << 1) + b_chi) ^ xorv) << 4;
            uint4 ah[4], bh[2];
            #pragma unroll
            for (int mf = 0; mf < 4; ++mf) ah[mf] = ldsm4(aB + (uint32_t)mf * 4096u + kxa);
            #pragma unroll
            for (int j = 0; j < 2; ++j) bh[j] = ldsm4(bBase[j] + kxb);
            #pragma unroll
            for (int mf = 0; mf < 4; ++mf)
                #pragma unroll
                for (int j = 0; j < 2; ++j) {
                    MMA4(acc[mf][2 * j],     ah[mf], bh[j].x, bh[j].y);
                    MMA4(acc[mf][2 * j + 1], ah[mf], bh[j].z, bh[j].w);
                }
        }

        // ---- epilogue: + b2, 8 rows x 8 contiguous cols per thread ----
        float4 bv0 = *reinterpret_cast<float4*>(&b2s[cb]);
        float4 bv1 = *reinterpret_cast<float4*>(&b2s[cb + 4]);
        #pragma unroll
        for (int mf = 0; mf < 4; ++mf) {
            int rr = 16 * mf + (lane >> 2);
            int row1 = orow_s[team][pb][rr];
            int row2 = orow_s[team][pb][rr + 8];
            if (row1 >= 0) {
                float* dst = out + (size_t)row1 * HH + cb;
                float4 v;
                v.x = acc[mf][0][0] + bv0.x; v.y = acc[mf][0][1] + bv0.y;
                v.z = acc[mf][1][0] + bv0.z; v.w = acc[mf][1][1] + bv0.w;
                *reinterpret_cast<float4*>(dst) = v;
                v.x = acc[mf][2][0] + bv1.x; v.y = acc[mf][2][1] + bv1.y;
                v.z = acc[mf][3][0] + bv1.z; v.w = acc[mf][3][1] + bv1.w;
                *reinterpret_cast<float4*>(dst + 4) = v;
            }
            if (row2 >= 0) {
                float* dst = out + (size_t)row2 * HH + cb;
                float4 v;
                v.x = acc[mf][0][2] + bv0.x; v.y = acc[mf][0][3] + bv0.y;
                v.z = acc[mf][1][2] + bv0.z; v.w = acc[mf][1][3] + bv0.w;
                *reinterpret_cast<float4*>(dst) = v;
                v.x = acc[mf][2][2] + bv1.x; v.y = acc[mf][2][3] + bv1.y;
                v.z = acc[mf][3][2] + bv1.z; v.w = acc[mf][3][3] + bv1.w;
                *reinterpret_cast<float4*>(dst + 4) = v;
            }
        }

        if (htid == 0) nt_s[team] = atomicAdd(&g_ticket, 1);
        asm volatile("bar.sync %0, %1;" :: "r"(barid), "r"(256) : "memory");  // readers of buf pb done; ticket visible
        int t2 = nt_s[team];
        issue_tile(t2, pb);   // refill buf pb one tile ahead

        cur = nxt; nxt = t2; pb ^= 1;
    }
}

extern "C" void kernel_launch(void* const* d_in, const int* in_sizes, int n_in,
                              void* d_out, int out_size) {
    const float* bbox = (const float*)d_in[0];
    const float* W1   = (const float*)d_in[1];
    const float* b1   = (const float*)d_in[2];
    const float* W2   = (const float*)d_in[3];
    const float* b2   = (const float*)d_in[4];
    const int*   npf  = (const int*)d_in[5];
    float* out = (float*)d_out;

    const int TOTROWS = in_sizes[0] / 4;               // N * T rows
    const int ntiles  = (TOTROWS + MT - 1) / MT;       // 64-row tiles
    const int nrowblk = ntiles * 4;                    // 16 rows per convert block

    int nsm = 148;
    cudaDeviceGetAttribute(&nsm, cudaDevAttrMultiProcessorCount, 0);

    cudaFuncSetAttribute(mma_kernel, cudaFuncAttributeMaxDynamicSharedMemorySize, DYN_SMEM);

    reset_ticket<<<1, 1>>>();
    convert_kernel<<<nrowblk + BB * NMAXX, 256>>>(bbox, W1, b1, npf, out, TOTROWS, nrowblk);
    mma_kernel<<<nsm, NTH, DYN_SMEM>>>(W2, b2, npf, out, TOTROWS, ntiles);
    (void)n_in; (void)out_size;
}

// round 13
// speedup vs baseline: 1.6285x; 1.6285x over previous
#include <cuda_runtime.h>
#include <cuda_fp16.h>
#include <cstdint>

#define BB 64
#define TT 32
#define NMAXX 64
#define HH 256      // output dim (N of GEMM)
#define HID 128     // mid dim (K of GEMM)
#define MT 64       // rows per team tile
#define NTH 512     // 16 warps: two independent teams of 8 warps

// dynamic smem (1024-aligned): A[team] 2x16KB, B 64KB
#define OFF_B 32768
#define DYN_SMEM (98304 + 1024)

__device__ __forceinline__ uint32_t smem_u32(const void* p) {
    uint32_t a;
    asm("{ .reg .u64 t; cvta.to.shared.u64 t, %1; cvt.u32.u64 %0, t; }" : "=r"(a) : "l"(p));
    return a;
}
__device__ __forceinline__ void sts32(uint32_t a, uint32_t v) {
    asm volatile("st.shared.b32 [%0], %1;" :: "r"(a), "r"(v) : "memory");
}
__device__ __forceinline__ void sts128(uint32_t a, uint4 v) {
    asm volatile("st.shared.v4.b32 [%0], {%1,%2,%3,%4};" :: "r"(a), "r"(v.x), "r"(v.y), "r"(v.z), "r"(v.w) : "memory");
}
__device__ __forceinline__ uint4 ldsm4(uint32_t a) {
    uint4 r;
    asm volatile("ldmatrix.sync.aligned.m8n8.x4.shared.b16 {%0,%1,%2,%3}, [%4];"
                 : "=r"(r.x), "=r"(r.y), "=r"(r.z), "=r"(r.w) : "r"(a));
    return r;
}
#define MMA4(c, a, bb0, bb1) \
    asm volatile("mma.sync.aligned.m16n8k16.row.col.f32.f16.f16.f32 " \
                 "{%0,%1,%2,%3},{%4,%5,%6,%7},{%8,%9},{%0,%1,%2,%3};" \
                 : "+f"((c)[0]), "+f"((c)[1]), "+f"((c)[2]), "+f"((c)[3]) \
                 : "r"((a).x), "r"((a).y), "r"((a).z), "r"((a).w), "r"(bb0), "r"(bb1))

__global__ __launch_bounds__(NTH, 1)
void fused_kernel(const float* __restrict__ bbox,
                  const float* __restrict__ W1, const float* __restrict__ b1,
                  const float* __restrict__ W2, const float* __restrict__ b2,
                  const int* __restrict__ npf,
                  float* __restrict__ out, int TOTROWS, int ntiles) {
    extern __shared__ char smraw[];
    __shared__ float W1s[4 * HID], b1s[HID], b2s[HH];
    __shared__ int sn[BB], st[BB + 1];
    __shared__ int orow_s[2][MT];

    const int tid  = threadIdx.x;
    const int lane = tid & 31, wid = tid >> 5;
    const int team = wid >> 3;        // 0/1: independent team
    const int hw   = wid & 7;         // warp within team = N-slice index
    const int htid = tid & 255;       // thread within team

    const uint32_t sb  = (smem_u32(smraw) + 1023) & ~1023u;
    const uint32_t A_T = sb + (uint32_t)team * 16384u;
    const uint32_t B_S = sb + OFF_B;

    // ---- stage small weights + batch counts ----
    for (int i = tid; i < 4 * HID; i += NTH) W1s[i] = W1[i];
    if (tid < HID) b1s[tid] = b1[tid];
    if (tid >= HID && tid < HID + HH) b2s[tid - HID] = b2[tid - HID];
    if (tid >= HID + HH && tid < HID + HH + BB) sn[tid - HID - HH] = npf[tid - HID - HH];
    __syncthreads();

    // ---- zerofill padded slots (round-robin over CTAs) ----
    for (int p = blockIdx.x; p < BB * NMAXX; p += gridDim.x) {
        int b = p >> 6, s = p & 63;
        if (s < sn[b]) continue;
        float4* dst = reinterpret_cast<float4*>(out + ((size_t)s * (BB * TT) + (size_t)b * TT) * HH);
        float4 z = make_float4(0.f, 0.f, 0.f, 0.f);
        #pragma unroll
        for (int i = 0; i < 4; ++i) dst[tid + i * NTH] = z;
    }

    // ---- exclusive scan ----
    if (tid == 0) {
        int s = 0;
        #pragma unroll
        for (int i = 0; i < BB; ++i) { st[i] = s; s += sn[i]; }
        st[BB] = s;
    }

    // ---- convert B = W2^T -> f16, permuted rows + 16B XOR swizzle ----
    // real col r (5-bit within 32-group): r = 16j + 4c + 2h + e
    //   -> mma row s = 16j + 8h + 2c + e
    // so thread (lane&3=c) owns real cols {16j + 4c + [0..3]}: contiguous 16B per store,
    // lanes 0-3 cover 64B contiguous per STG instruction (full sectors).
    {
        const int n  = tid & 255;
        const int kh = tid >> 8;           // K half (32 pairs each)
        const int r = n & 31;
        const int s = 16 * ((r >> 4) & 1) + 8 * ((r >> 1) & 1) + 2 * ((r >> 2) & 3) + (r & 1);
        const int m = (n & ~31) | s;
        const uint32_t mb = (uint32_t)m * 256u;
        const uint32_t mx = (uint32_t)(m & 7);
        #pragma unroll 4
        for (int q = 0; q < 32; ++q) {
            int jp = kh * 32 + q;
            int j = 2 * jp;
            float w0 = __ldg(&W2[(size_t)j * HH + n]);
            float w1 = __ldg(&W2[(size_t)(j + 1) * HH + n]);
            __half2 hi = __floats2half2_rn(w0, w1);
            uint32_t byte = mb + ((((uint32_t)jp >> 2) ^ mx) << 4) + (((uint32_t)jp & 3) << 2);
            sts32(B_S + byte, *reinterpret_cast<uint32_t*>(&hi));
        }
    }

    // ---- per-thread geometry: warp tile 64(M) x 32(N), warp hw owns cols [32hw, 32hw+32) ----
    const uint32_t xorv = (uint32_t)(lane & 7);
    const int a_row = (lane & 7) + ((lane >> 3) & 1) * 8;
    const uint32_t a_chi = (uint32_t)(lane >> 4);
    const int b_row = (lane & 7) + (lane >> 4) * 8;
    const uint32_t b_chi = (uint32_t)((lane >> 3) & 1);

    const uint32_t aOff0 = (uint32_t)a_row * 256u;          // + mf*4096 + kxa
    uint32_t bBase[2];
    #pragma unroll
    for (int j = 0; j < 2; ++j)
        bBase[j] = B_S + (uint32_t)(hw * 32 + j * 16 + b_row) * 256u;

    // A-convert geometry (256 threads per team): row 0..63, k-quarter 0..3
    const int cr = htid & 63;
    const int kq = htid >> 6;
    const uint32_t crb = (uint32_t)cr * 256u;
    const uint32_t crx = (uint32_t)(cr & 7);

    const int cb = hw * 32 + (lane & 3) * 4;  // first-store col base (second at +16)
    const int barid = team + 1;
    const int sstride = gridDim.x * 2;
    const int tile0 = blockIdx.x * 2 + team;

    __syncthreads();  // B, scan, weights visible; last full-block barrier

    // ---- prefetch first tile's bbox row ----
    float4 x = make_float4(0.f, 0.f, 0.f, 0.f);
    {
        int grow = tile0 * MT + cr;
        if (tile0 < ntiles && grow < TOTROWS)
            x = __ldg(reinterpret_cast<const float4*>(bbox) + grow);
    }

    for (int tile = tile0; tile < ntiles; tile += sstride) {
        asm volatile("bar.sync %0, %1;" :: "r"(barid), "r"(256) : "memory");  // A readers done

        // ---- layer 1 fused + fp16 into A (uses prefetched x) ----
        {
            int grow = tile * MT + cr;
            if (kq == 0) {
                int orow = -1;
                if (grow < TOTROWS) {
                    int box = grow >> 5;
                    int lo = 0, hi = BB - 1;
                    #pragma unroll
                    for (int step = 0; step < 6; ++step) {
                        int mid = (lo + hi + 1) >> 1;
                        if (st[mid] <= box) lo = mid; else hi = mid - 1;
                    }
                    orow = (box - st[lo]) * (BB * TT) + lo * TT + (grow & 31);
                }
                orow_s[team][cr] = orow;
            }
            #pragma unroll
            for (int cc = 0; cc < 4; ++cc) {
                int chunk = kq * 4 + cc;
                int j0 = chunk * 8;
                uint32_t hiw[4];
                #pragma unroll
                for (int p = 0; p < 4; ++p) {
                    int j = j0 + 2 * p;
                    float h0 = fmaf(x.x, W1s[j],     fmaf(x.y, W1s[HID + j],     fmaf(x.z, W1s[2 * HID + j],     fmaf(x.w, W1s[3 * HID + j],     b1s[j]))));
                    float h1 = fmaf(x.x, W1s[j + 1], fmaf(x.y, W1s[HID + j + 1], fmaf(x.z, W1s[2 * HID + j + 1], fmaf(x.w, W1s[3 * HID + j + 1], b1s[j + 1]))));
                    __half2 hv = __floats2half2_rn(fmaxf(h0, 0.f), fmaxf(h1, 0.f));
                    hiw[p] = *reinterpret_cast<uint32_t*>(&hv);
                }
                uint32_t byte = crb + (((uint32_t)chunk ^ crx) << 4);
                sts128(A_T + byte, make_uint4(hiw[0], hiw[1], hiw[2], hiw[3]));
            }
        }

        // ---- prefetch next tile's bbox row (overlaps MMA + epilogue) ----
        {
            int nxt = tile + sstride;
            int grow = nxt * MT + cr;
            float4 xn = make_float4(0.f, 0.f, 0.f, 0.f);
            if (nxt < ntiles && grow < TOTROWS)
                xn = __ldg(reinterpret_cast<const float4*>(bbox) + grow);
            x = xn;
        }
        asm volatile("bar.sync %0, %1;" :: "r"(barid), "r"(256) : "memory");

        // ---- MMA mainloop: single fp16 product, K=128, warp tile 64x32 ----
        float acc[4][4][4];   // [mf][q=2j+h][reg]
        #pragma unroll
        for (int mf = 0; mf < 4; ++mf)
            #pragma unroll
            for (int q = 0; q < 4; ++q)
                #pragma unroll
                for (int e = 0; e < 4; ++e) acc[mf][q][e] = 0.f;

        #pragma unroll 1
        for (int kc = 0; kc < 8; ++kc) {
            uint32_t kxa = ((((uint32_t)kc << 1) + a_chi) ^ xorv) << 4;
            uint32_t kxb = ((((uint32_t)kc << 1) + b_chi) ^ xorv) << 4;
            uint4 ah[4], bh[2];
            #pragma unroll
            for (int mf = 0; mf < 4; ++mf) ah[mf] = ldsm4(A_T + aOff0 + (uint32_t)mf * 4096u + kxa);
            #pragma unroll
            for (int j = 0; j < 2; ++j) bh[j] = ldsm4(bBase[j] + kxb);
            #pragma unroll
            for (int mf = 0; mf < 4; ++mf)
                #pragma unroll
                for (int j = 0; j < 2; ++j) {
                    MMA4(acc[mf][2 * j],     ah[mf], bh[j].x, bh[j].y);
                    MMA4(acc[mf][2 * j + 1], ah[mf], bh[j].z, bh[j].w);
                }
        }

        // ---- epilogue: + b2, contiguous 64B per STG across lanes 0-3 ----
        // thread covers real cols [cb, cb+4) (j=0) and [cb+16, cb+20) (j=1)
        // float4 components = (h,e) = (0,0),(0,1),(1,0),(1,1) -> acc[2j+h][e-pair]
        float4 bv0 = *reinterpret_cast<float4*>(&b2s[cb]);
        float4 bv1 = *reinterpret_cast<float4*>(&b2s[cb + 16]);
        #pragma unroll
        for (int mf = 0; mf < 4; ++mf) {
            int rr = 16 * mf + (lane >> 2);
            int row1 = orow_s[team][rr];
            int row2 = orow_s[team][rr + 8];
            if (row1 >= 0) {
                float* dst = out + (size_t)row1 * HH + cb;
                float4 v;
                v.x = acc[mf][0][0] + bv0.x; v.y = acc[mf][0][1] + bv0.y;
                v.z = acc[mf][1][0] + bv0.z; v.w = acc[mf][1][1] + bv0.w;
                *reinterpret_cast<float4*>(dst) = v;
                v.x = acc[mf][2][0] + bv1.x; v.y = acc[mf][2][1] + bv1.y;
                v.z = acc[mf][3][0] + bv1.z; v.w = acc[mf][3][1] + bv1.w;
                *reinterpret_cast<float4*>(dst + 16) = v;
            }
            if (row2 >= 0) {
                float* dst = out + (size_t)row2 * HH + cb;
                float4 v;
                v.x = acc[mf][0][2] + bv0.x; v.y = acc[mf][0][3] + bv0.y;
                v.z = acc[mf][1][2] + bv0.z; v.w = acc[mf][1][3] + bv0.w;
                *reinterpret_cast<float4*>(dst) = v;
                v.x = acc[mf][2][2] + bv1.x; v.y = acc[mf][2][3] + bv1.y;
                v.z = acc[mf][3][2] + bv1.z; v.w = acc[mf][3][3] + bv1.w;
                *reinterpret_cast<float4*>(dst + 16) = v;
            }
        }
    }
}

extern "C" void kernel_launch(void* const* d_in, const int* in_sizes, int n_in,
                              void* d_out, int out_size) {
    const float* bbox = (const float*)d_in[0];
    const float* W1   = (const float*)d_in[1];
    const float* b1   = (const float*)d_in[2];
    const float* W2   = (const float*)d_in[3];
    const float* b2   = (const float*)d_in[4];
    const int*   npf  = (const int*)d_in[5];
    float* out = (float*)d_out;

    const int TOTROWS = in_sizes[0] / 4;               // N * T rows
    const int ntiles  = (TOTROWS + MT - 1) / MT;       // 64-row tiles

    int nsm = 148;
    cudaDeviceGetAttribute(&nsm, cudaDevAttrMultiProcessorCount, 0);

    cudaFuncSetAttribute(fused_kernel, cudaFuncAttributeMaxDynamicSharedMemorySize, DYN_SMEM);
    fused_kernel<<<nsm, NTH, DYN_SMEM>>>(bbox, W1, b1, W2, b2, npf, out, TOTROWS, ntiles);
    (void)n_in; (void)out_size;
}

// round 14
// speedup vs baseline: 1.7064x; 1.0478x over previous
#include <cuda_runtime.h>
#include <cuda_fp16.h>
#include <cstdint>

#define BB 64
#define TT 32
#define NMAXX 64
#define HH 256      // output dim (N of GEMM)
#define HID 128     // mid dim (K of GEMM)
#define MT 64       // rows per team tile
#define NTH 1024    // 32 warps: two independent teams of 16 warps (2M x 8N grid)

// dynamic smem (1024-aligned): A[team] 2x16KB, B 64KB
#define OFF_B 32768
#define DYN_SMEM (98304 + 1024)

__device__ __forceinline__ uint32_t smem_u32(const void* p) {
    uint32_t a;
    asm("{ .reg .u64 t; cvta.to.shared.u64 t, %1; cvt.u32.u64 %0, t; }" : "=r"(a) : "l"(p));
    return a;
}
__device__ __forceinline__ void sts32(uint32_t a, uint32_t v) {
    asm volatile("st.shared.b32 [%0], %1;" :: "r"(a), "r"(v) : "memory");
}
__device__ __forceinline__ void sts128(uint32_t a, uint4 v) {
    asm volatile("st.shared.v4.b32 [%0], {%1,%2,%3,%4};" :: "r"(a), "r"(v.x), "r"(v.y), "r"(v.z), "r"(v.w) : "memory");
}
__device__ __forceinline__ uint4 ldsm4(uint32_t a) {
    uint4 r;
    asm volatile("ldmatrix.sync.aligned.m8n8.x4.shared.b16 {%0,%1,%2,%3}, [%4];"
                 : "=r"(r.x), "=r"(r.y), "=r"(r.z), "=r"(r.w) : "r"(a));
    return r;
}
#define MMA4(c, a, bb0, bb1) \
    asm volatile("mma.sync.aligned.m16n8k16.row.col.f32.f16.f16.f32 " \
                 "{%0,%1,%2,%3},{%4,%5,%6,%7},{%8,%9},{%0,%1,%2,%3};" \
                 : "+f"((c)[0]), "+f"((c)[1]), "+f"((c)[2]), "+f"((c)[3]) \
                 : "r"((a).x), "r"((a).y), "r"((a).z), "r"((a).w), "r"(bb0), "r"(bb1))

__global__ __launch_bounds__(NTH, 1)
void fused_kernel(const float* __restrict__ bbox,
                  const float* __restrict__ W1, const float* __restrict__ b1,
                  const float* __restrict__ W2, const float* __restrict__ b2,
                  const int* __restrict__ npf,
                  float* __restrict__ out, int TOTROWS, int ntiles) {
    extern __shared__ char smraw[];
    __shared__ float W1s[4 * HID], b1s[HID], b2s[HH];
    __shared__ int sn[BB], st[BB + 1];
    __shared__ int orow_s[2][MT];

    const int tid  = threadIdx.x;
    const int lane = tid & 31, wid = tid >> 5;
    const int team = wid >> 4;        // 0/1: independent team of 16 warps
    const int tw   = wid & 15;        // warp within team
    const int wm   = tw >> 3;         // M half (0/1)
    const int wn   = tw & 7;          // N slice
    const int htid = tid & 511;       // thread within team

    const uint32_t sb  = (smem_u32(smraw) + 1023) & ~1023u;
    const uint32_t A_T = sb + (uint32_t)team * 16384u;
    const uint32_t B_S = sb + OFF_B;

    // ---- stage small weights + batch counts ----
    if (tid < 4 * HID) W1s[tid] = W1[tid];
    if (tid >= 512 && tid < 512 + HID) b1s[tid - 512] = b1[tid - 512];
    if (tid >= 640 && tid < 640 + HH) b2s[tid - 640] = b2[tid - 640];
    if (tid >= 896 && tid < 896 + BB) sn[tid - 896] = npf[tid - 896];
    __syncthreads();

    // ---- zerofill padded slots (round-robin over CTAs) ----
    for (int p = blockIdx.x; p < BB * NMAXX; p += gridDim.x) {
        int b = p >> 6, s = p & 63;
        if (s < sn[b]) continue;
        float4* dst = reinterpret_cast<float4*>(out + ((size_t)s * (BB * TT) + (size_t)b * TT) * HH);
        float4 z = make_float4(0.f, 0.f, 0.f, 0.f);
        #pragma unroll
        for (int i = 0; i < 2; ++i) dst[tid + i * NTH] = z;
    }

    // ---- exclusive scan ----
    if (tid == 0) {
        int s = 0;
        #pragma unroll
        for (int i = 0; i < BB; ++i) { st[i] = s; s += sn[i]; }
        st[BB] = s;
    }

    // ---- convert B = W2^T -> f16, permuted rows + 16B XOR swizzle ----
    // real col r (within 32-group): r = 16j + 4c + 2h + e -> mma row s = 16j + 8h + 2c + e
    {
        const int n  = tid & 255;
        const int kh = tid >> 8;           // 0..3, 16 pairs each
        const int r = n & 31;
        const int s = 16 * ((r >> 4) & 1) + 8 * ((r >> 1) & 1) + 2 * ((r >> 2) & 3) + (r & 1);
        const int m = (n & ~31) | s;
        const uint32_t mb = (uint32_t)m * 256u;
        const uint32_t mx = (uint32_t)(m & 7);
        #pragma unroll 4
        for (int q = 0; q < 16; ++q) {
            int jp = kh * 16 + q;
            int j = 2 * jp;
            float w0 = __ldg(&W2[(size_t)j * HH + n]);
            float w1 = __ldg(&W2[(size_t)(j + 1) * HH + n]);
            __half2 hi = __floats2half2_rn(w0, w1);
            uint32_t byte = mb + ((((uint32_t)jp >> 2) ^ mx) << 4) + (((uint32_t)jp & 3) << 2);
            sts32(B_S + byte, *reinterpret_cast<uint32_t*>(&hi));
        }
    }

    // ---- per-thread geometry: warp tile 32(M) x 32(N) ----
    const uint32_t xorv = (uint32_t)(lane & 7);
    const int a_row = (lane & 7) + ((lane >> 3) & 1) * 8;
    const uint32_t a_chi = (uint32_t)(lane >> 4);
    const int b_row = (lane & 7) + (lane >> 4) * 8;
    const uint32_t b_chi = (uint32_t)((lane >> 3) & 1);

    const uint32_t aOff0 = (uint32_t)(wm * 32 + a_row) * 256u;   // + mf*4096 + kxa
    uint32_t bBase[2];
    #pragma unroll
    for (int j = 0; j < 2; ++j)
        bBase[j] = B_S + (uint32_t)(wn * 32 + j * 16 + b_row) * 256u;

    // A-convert geometry (512 threads per team): row 0..63, k-eighth 0..7 (16 cols each)
    const int cr  = htid & 63;
    const int kq8 = htid >> 6;
    const uint32_t crb = (uint32_t)cr * 256u;
    const uint32_t crx = (uint32_t)(cr & 7);

    const int cb = wn * 32 + (lane & 3) * 4;  // first-store col base (second at +16)
    const int barid = team + 1;
    const int sstride = gridDim.x * 2;
    const int tile0 = blockIdx.x * 2 + team;

    __syncthreads();  // B, scan, weights visible; last full-block barrier

    // ---- prefetch first tile's bbox row ----
    float4 x = make_float4(0.f, 0.f, 0.f, 0.f);
    {
        int grow = tile0 * MT + cr;
        if (tile0 < ntiles && grow < TOTROWS)
            x = __ldg(reinterpret_cast<const float4*>(bbox) + grow);
    }

    for (int tile = tile0; tile < ntiles; tile += sstride) {
        asm volatile("bar.sync %0, %1;" :: "r"(barid), "r"(512) : "memory");  // A readers done

        // ---- layer 1 fused + fp16 into A (uses prefetched x): 2 chunks per thread ----
        {
            int grow = tile * MT + cr;
            if (kq8 == 0) {
                int orow = -1;
                if (grow < TOTROWS) {
                    int box = grow >> 5;
                    int lo = 0, hi = BB - 1;
                    #pragma unroll
                    for (int step = 0; step < 6; ++step) {
                        int mid = (lo + hi + 1) >> 1;
                        if (st[mid] <= box) lo = mid; else hi = mid - 1;
                    }
                    orow = (box - st[lo]) * (BB * TT) + lo * TT + (grow & 31);
                }
                orow_s[team][cr] = orow;
            }
            #pragma unroll
            for (int cc = 0; cc < 2; ++cc) {
                int chunk = kq8 * 2 + cc;
                int j0 = chunk * 8;
                uint32_t hiw[4];
                #pragma unroll
                for (int p = 0; p < 4; ++p) {
                    int j = j0 + 2 * p;
                    float h0 = fmaf(x.x, W1s[j],     fmaf(x.y, W1s[HID + j],     fmaf(x.z, W1s[2 * HID + j],     fmaf(x.w, W1s[3 * HID + j],     b1s[j]))));
                    float h1 = fmaf(x.x, W1s[j + 1], fmaf(x.y, W1s[HID + j + 1], fmaf(x.z, W1s[2 * HID + j + 1], fmaf(x.w, W1s[3 * HID + j + 1], b1s[j + 1]))));
                    __half2 hv = __floats2half2_rn(fmaxf(h0, 0.f), fmaxf(h1, 0.f));
                    hiw[p] = *reinterpret_cast<uint32_t*>(&hv);
                }
                uint32_t byte = crb + (((uint32_t)chunk ^ crx) << 4);
                sts128(A_T + byte, make_uint4(hiw[0], hiw[1], hiw[2], hiw[3]));
            }
        }

        // ---- prefetch next tile's bbox row (overlaps MMA + epilogue) ----
        {
            int nxt = tile + sstride;
            int grow = nxt * MT + cr;
            float4 xn = make_float4(0.f, 0.f, 0.f, 0.f);
            if (nxt < ntiles && grow < TOTROWS)
                xn = __ldg(reinterpret_cast<const float4*>(bbox) + grow);
            x = xn;
        }
        asm volatile("bar.sync %0, %1;" :: "r"(barid), "r"(512) : "memory");

        // ---- MMA mainloop: single fp16 product, K=128, warp tile 32x32 ----
        float acc[2][4][4];   // [mf][q=2j+h][reg]
        #pragma unroll
        for (int mf = 0; mf < 2; ++mf)
            #pragma unroll
            for (int q = 0; q < 4; ++q)
                #pragma unroll
                for (int e = 0; e < 4; ++e) acc[mf][q][e] = 0.f;

        #pragma unroll 1
        for (int kc = 0; kc < 8; ++kc) {
            uint32_t kxa = ((((uint32_t)kc << 1) + a_chi) ^ xorv) << 4;
            uint32_t kxb = ((((uint32_t)kc << 1) + b_chi) ^ xorv) << 4;
            uint4 ah[2], bh[2];
            #pragma unroll
            for (int mf = 0; mf < 2; ++mf) ah[mf] = ldsm4(A_T + aOff0 + (uint32_t)mf * 4096u + kxa);
            #pragma unroll
            for (int j = 0; j < 2; ++j) bh[j] = ldsm4(bBase[j] + kxb);
            #pragma unroll
            for (int mf = 0; mf < 2; ++mf)
                #pragma unroll
                for (int j = 0; j < 2; ++j) {
                    MMA4(acc[mf][2 * j],     ah[mf], bh[j].x, bh[j].y);
                    MMA4(acc[mf][2 * j + 1], ah[mf], bh[j].z, bh[j].w);
                }
        }

        // ---- epilogue: + b2, contiguous 64B per STG across lanes 0-3 ----
        float4 bv0 = *reinterpret_cast<float4*>(&b2s[cb]);
        float4 bv1 = *reinterpret_cast<float4*>(&b2s[cb + 16]);
        #pragma unroll
        for (int mf = 0; mf < 2; ++mf) {
            int rr = wm * 32 + 16 * mf + (lane >> 2);
            int row1 = orow_s[team][rr];
            int row2 = orow_s[team][rr + 8];
            if (row1 >= 0) {
                float* dst = out + (size_t)row1 * HH + cb;
                float4 v;
                v.x = acc[mf][0][0] + bv0.x; v.y = acc[mf][0][1] + bv0.y;
                v.z = acc[mf][1][0] + bv0.z; v.w = acc[mf][1][1] + bv0.w;
                *reinterpret_cast<float4*>(dst) = v;
                v.x = acc[mf][2][0] + bv1.x; v.y = acc[mf][2][1] + bv1.y;
                v.z = acc[mf][3][0] + bv1.z; v.w = acc[mf][3][1] + bv1.w;
                *reinterpret_cast<float4*>(dst + 16) = v;
            }
            if (row2 >= 0) {
                float* dst = out + (size_t)row2 * HH + cb;
                float4 v;
                v.x = acc[mf][0][2] + bv0.x; v.y = acc[mf][0][3] + bv0.y;
                v.z = acc[mf][1][2] + bv0.z; v.w = acc[mf][1][3] + bv0.w;
                *reinterpret_cast<float4*>(dst) = v;
                v.x = acc[mf][2][2] + bv1.x; v.y = acc[mf][2][3] + bv1.y;
                v.z = acc[mf][3][2] + bv1.z; v.w = acc[mf][3][3] + bv1.w;
                *reinterpret_cast<float4*>(dst + 16) = v;
            }
        }
    }
}

extern "C" void kernel_launch(void* const* d_in, const int* in_sizes, int n_in,
                              void* d_out, int out_size) {
    const float* bbox = (const float*)d_in[0];
    const float* W1   = (const float*)d_in[1];
    const float* b1   = (const float*)d_in[2];
    const float* W2   = (const float*)d_in[3];
    const float* b2   = (const float*)d_in[4];
    const int*   npf  = (const int*)d_in[5];
    float* out = (float*)d_out;

    const int TOTROWS = in_sizes[0] / 4;               // N * T rows
    const int ntiles  = (TOTROWS + MT - 1) / MT;       // 64-row tiles

    int nsm = 148;
    cudaDeviceGetAttribute(&nsm, cudaDevAttrMultiProcessorCount, 0);

    cudaFuncSetAttribute(fused_kernel, cudaFuncAttributeMaxDynamicSharedMemorySize, DYN_SMEM);
    fused_kernel<<<nsm, NTH, DYN_SMEM>>>(bbox, W1, b1, W2, b2, npf, out, TOTROWS, ntiles);
    (void)n_in; (void)out_size;
}